// round 11
// baseline (speedup 1.0000x reference)
#include <cuda_runtime.h>

// LearnedClassVectors: HU bucketize (10 bins) -> 12-dim embedding gather ->
// 4x4x4 patch unfold -> channel-major output (2, 768, 32, 32, 32) fp32.
//
//   x:       (2,1,128,128,128) fp32   d_in[0]
//   vectors: (10,12)           fp32   d_in[1]
//   out:     (2,768,32,32,32)  fp32   50,331,648 elements
//
// R10: R3 trunk (scalar LDS gather -- proven fastest) + 256-bit stores
// (sm_103a st.global.v8.f32). One thread owns 32 consecutive w voxels;
// lanes 0-3 of a warp each store 32B per STG.256 -> 8 fully packed 128B
// lines per store instruction. Store instruction count halved vs R3.
// 512 blocks = single wave on 148 SMs.

static __device__ __forceinline__ unsigned hu_bin(float v) {
    // searchsorted(edges, v, side='right') == count of edges <= v
    unsigned b = 0;
    b += (v >= -1000.0f);
    b += (v >=   -75.0f);
    b += (v >=     0.0f);
    b += (v >=    15.0f);
    b += (v >=    25.0f);
    b += (v >=    40.0f);
    b += (v >=    50.0f);
    b += (v >=   200.0f);
    b += (v >=  1000.0f);
    return b;
}

static __device__ __forceinline__ void stg256(float* p,
        float f0, float f1, float f2, float f3,
        float f4, float f5, float f6, float f7) {
    asm volatile(
        "st.global.v8.f32 [%0], {%1,%2,%3,%4,%5,%6,%7,%8};"
        :: "l"(p), "f"(f0), "f"(f1), "f"(f2), "f"(f3),
                   "f"(f4), "f"(f5), "f"(f6), "f"(f7)
        : "memory");
}

__global__ __launch_bounds__(256)
void lcv_kernel(const float* __restrict__ x,
                const float* __restrict__ vectors,
                float* __restrict__ out) {
    __shared__ float s_vec[10 * 12];
    if (threadIdx.x < 120) s_vec[threadIdx.x] = vectors[threadIdx.x];
    __syncthreads();

    unsigned tid = blockIdx.x * blockDim.x + threadIdx.x;   // 0 .. 131071
    int tp = tid & 3;            // w-chunk: covers w = 32*tp .. 32*tp+31
    unsigned r = tid >> 2;
    int h = r & 127; r >>= 7;
    int d = r & 127; r >>= 7;
    int b = (int)r;              // 0..1

    // ---- 32 consecutive x values (8x LDG.128; warp reads 4KB contiguous) ----
    const float4* xp = (const float4*)(x +
        ((size_t)((b * 128 + d) * 128 + h) * 128 + (unsigned)tp * 32u));
    float4 xv[8];
#pragma unroll
    for (int i = 0; i < 8; i++) xv[i] = xp[i];

    // bins for 32 voxels: pack the 8 gw-bins of each pw into one uint (4b each)
    unsigned bp0 = 0, bp1 = 0, bp2 = 0, bp3 = 0;
#pragma unroll
    for (int g = 0; g < 8; g++) {
        bp0 |= hu_bin(xv[g].x) << (4 * g);
        bp1 |= hu_bin(xv[g].y) << (4 * g);
        bp2 |= hu_bin(xv[g].z) << (4 * g);
        bp3 |= hu_bin(xv[g].w) << (4 * g);
    }
    unsigned bpp[4] = { bp0, bp1, bp2, bp3 };

    // ---- output addressing ----
    int gd = d >> 2, pd = d & 3;
    int gh = h >> 2, ph = h & 3;
    float* ob = out + (size_t)b * (768u * 32768u)
                    + (unsigned)gd * 1024u + (unsigned)gh * 32u
                    + (unsigned)tp * 8u;                 // 32B-aligned
    int chbase = (pd * 16 + ph * 4) * 12;   // + pw*12 + v

#pragma unroll
    for (int pw = 0; pw < 4; pw++) {
        unsigned bp = bpp[pw];
        // row base offsets into the shared table for the 8 gw voxels
        unsigned ro[8];
#pragma unroll
        for (int g = 0; g < 8; g++) ro[g] = ((bp >> (4 * g)) & 15u) * 12u;

        float* op = ob + (size_t)(chbase + pw * 12) * 32768u;
#pragma unroll
        for (int v = 0; v < 12; v++) {
            // 8 scalar LDS.32 (<=2-way bank conflicts), then one STG.256:
            // 8 consecutive gw of one output channel, 32B per lane,
            // 4 lanes = one full 128B line, 8 lines per warp instruction.
            stg256(op,
                   s_vec[ro[0] + v], s_vec[ro[1] + v],
                   s_vec[ro[2] + v], s_vec[ro[3] + v],
                   s_vec[ro[4] + v], s_vec[ro[5] + v],
                   s_vec[ro[6] + v], s_vec[ro[7] + v]);
            op += 32768u;        // next channel, same spatial position
        }
    }
}

extern "C" void kernel_launch(void* const* d_in, const int* in_sizes, int n_in,
                              void* d_out, int out_size) {
    const float* x       = (const float*)d_in[0];
    const float* vectors = (const float*)d_in[1];
    float* out           = (float*)d_out;

    // 131072 threads, 32 w-voxels each: 512 blocks -> single wave
    lcv_kernel<<<512, 256>>>(x, vectors, out);
}

// round 14
// speedup vs baseline: 1.3701x; 1.3701x over previous
#include <cuda_runtime.h>

// LearnedClassVectors: HU bucketize (10 bins) -> 12-dim embedding gather ->
// 4x4x4 patch unfold -> channel-major output (2, 768, 32, 32, 32) fp32.
//
//   x:       (2,1,128,128,128) fp32   d_in[0]
//   vectors: (10,12)           fp32   d_in[1]
//   out:     (2,768,32,32,32)  fp32   50,331,648 elements
//
// R11 = R3 trunk with ONE change: warp lane remap. tid bits [4:3] now carry
// gh_low2 instead of h_low2(=ph), so all 32 lanes of a warp write the SAME
// output channel and their spatial offsets (gh_lo*32 + tw*4) tile one
// contiguous 512B-aligned block per STG.128 instruction (vs R3's 4 full
// 128B lines scattered 1.5MB apart). Per-thread work identical to R3.

static __device__ __forceinline__ int hu_bin(float v) {
    // searchsorted(edges, v, side='right') == count of edges <= v
    int b = 0;
    b += (v >= -1000.0f);
    b += (v >=   -75.0f);
    b += (v >=     0.0f);
    b += (v >=    15.0f);
    b += (v >=    25.0f);
    b += (v >=    40.0f);
    b += (v >=    50.0f);
    b += (v >=   200.0f);
    b += (v >=  1000.0f);
    return b;
}

__global__ __launch_bounds__(256)
void lcv_kernel(const float* __restrict__ x,
                const float* __restrict__ vectors,
                float* __restrict__ out) {
    // 10 rows x 12 floats; stride 12 spreads row bases across banks
    __shared__ float s_vec[10 * 12];
    if (threadIdx.x < 120) s_vec[threadIdx.x] = vectors[threadIdx.x];
    __syncthreads();

    unsigned tid = blockIdx.x * blockDim.x + threadIdx.x;   // 0 .. 262143
    // bit layout: [2:0]=tw  [4:3]=gh_lo  [6:5]=ph  [9:7]=gh_hi  [16:10]=d  [17]=b
    int tw    = tid & 7;
    int gh_lo = (tid >> 3) & 3;
    int ph    = (tid >> 5) & 3;
    int gh_hi = (tid >> 7) & 7;
    int d     = (tid >> 10) & 127;
    int b     = (int)(tid >> 17);

    int gh = gh_hi * 4 + gh_lo;
    int h  = gh * 4 + ph;
    int gd = d >> 2, pd = d & 3;

    // ---- 16 consecutive x values (4x LDG.128; warp = 4 x 512B chunks) ----
    const float4* xp = (const float4*)(x +
        ((size_t)((b * 128 + d) * 128 + h) * 128 + (unsigned)tw * 16u));
    float4 xv0 = xp[0];
    float4 xv1 = xp[1];
    float4 xv2 = xp[2];
    float4 xv3 = xp[3];

    // bins[gwi][pw]: voxel (gw = 4*tw + gwi, pw) is xv[gwi] component pw
    int bins[4][4];
    bins[0][0] = hu_bin(xv0.x); bins[0][1] = hu_bin(xv0.y);
    bins[0][2] = hu_bin(xv0.z); bins[0][3] = hu_bin(xv0.w);
    bins[1][0] = hu_bin(xv1.x); bins[1][1] = hu_bin(xv1.y);
    bins[1][2] = hu_bin(xv1.z); bins[1][3] = hu_bin(xv1.w);
    bins[2][0] = hu_bin(xv2.x); bins[2][1] = hu_bin(xv2.y);
    bins[2][2] = hu_bin(xv2.z); bins[2][3] = hu_bin(xv2.w);
    bins[3][0] = hu_bin(xv3.x); bins[3][1] = hu_bin(xv3.y);
    bins[3][2] = hu_bin(xv3.z); bins[3][3] = hu_bin(xv3.w);

    // ---- output addressing: all lanes of a warp share the channel; the
    // warp's 32 float4 stores tile one contiguous 512B block ----
    float* ob = out + (size_t)b * (768u * 32768u)
                    + (unsigned)gd * 1024u + (unsigned)gh * 32u
                    + (unsigned)tw * 4u;
    int chbase = (pd * 16 + ph * 4) * 12;   // + pw*12 + v

#pragma unroll
    for (int pw = 0; pw < 4; pw++) {
        const float* r0 = &s_vec[bins[0][pw] * 12];
        const float* r1 = &s_vec[bins[1][pw] * 12];
        const float* r2 = &s_vec[bins[2][pw] * 12];
        const float* r3 = &s_vec[bins[3][pw] * 12];

        // stage the 4 embedding rows into registers (scalar LDS, R3-proven)
        float a0[12], a1[12], a2[12], a3[12];
#pragma unroll
        for (int v = 0; v < 12; v++) {
            a0[v] = r0[v]; a1[v] = r1[v]; a2[v] = r2[v]; a3[v] = r3[v];
        }

        float* op = ob + (size_t)(chbase + pw * 12) * 32768u;
#pragma unroll
        for (int v = 0; v < 12; v++) {
            // 4 consecutive gw of one output channel -> one STG.128;
            // warp-wide: one contiguous 512B burst
            *(float4*)op = make_float4(a0[v], a1[v], a2[v], a3[v]);
            op += 32768;                     // next channel, same spatial
        }
    }
}

extern "C" void kernel_launch(void* const* d_in, const int* in_sizes, int n_in,
                              void* d_out, int out_size) {
    const float* x       = (const float*)d_in[0];
    const float* vectors = (const float*)d_in[1];
    float* out           = (float*)d_out;

    // 262144 threads, one 16-voxel w-tile each: 1024 blocks
    lcv_kernel<<<1024, 256>>>(x, vectors, out);
}